// round 8
// baseline (speedup 1.0000x reference)
#include <cuda_runtime.h>
#include <cstdint>

// ============================ problem dims ============================
#define N_IMG 16
#define H_IMG 112
#define W_IMG 112
#define C_IN  256
#define C_OUT 256
#define H_PAD 114
#define W_PAD 114

// padded, packed int8 activations: [N][H_PAD][W_PAD][C_IN]  (~53 MB)
__device__ __align__(1024) uint8_t g_xp[(size_t)N_IMG * H_PAD * W_PAD * C_IN];
// packed int8 weights, tap-major: [9][C_OUT][C_IN]
__device__ __align__(1024) uint8_t g_w8[9 * C_OUT * C_IN];

// ============================ pack kernels ============================
__global__ void pack_x_kernel(const int* __restrict__ x) {
    int64_t i = (int64_t)blockIdx.x * blockDim.x + threadIdx.x;
    const int64_t total = (int64_t)N_IMG * H_PAD * W_PAD * 64;  // 4-byte words
    if (i >= total) return;
    int c4 = (int)(i & 63);
    int64_t p = i >> 6;
    int wp = (int)(p % W_PAD);
    int64_t t = p / W_PAD;
    int hp = (int)(t % H_PAD);
    int n  = (int)(t / H_PAD);
    uint32_t word = 0;
    if (hp >= 1 && hp <= H_IMG && wp >= 1 && wp <= W_IMG) {
        const int4 v = *reinterpret_cast<const int4*>(
            x + ((((int64_t)n * H_IMG + (hp - 1)) * W_IMG + (wp - 1)) * C_IN + c4 * 4));
        word = (v.x & 255) | ((v.y & 255) << 8) | ((v.z & 255) << 16) | ((v.w & 255) << 24);
    }
    reinterpret_cast<uint32_t*>(g_xp)[i] = word;
}

__global__ void pack_w_kernel(const int* __restrict__ w) {
    int i = blockIdx.x * blockDim.x + threadIdx.x;
    const int total = 9 * C_OUT * 64;
    if (i >= total) return;
    int c4 = i & 63;
    int t = i >> 6;
    int co = t % C_OUT;
    int tap = t / C_OUT;  // kh*3 + kw
    const int4 v = *reinterpret_cast<const int4*>(
        w + (((int64_t)co * 9 + tap) * C_IN + c4 * 4));
    uint32_t word = (v.x & 255) | ((v.y & 255) << 8) | ((v.z & 255) << 16) | ((v.w & 255) << 24);
    reinterpret_cast<uint32_t*>(g_w8)[i] = word;
}

// ============================ asm helpers ============================
#define CP_ASYNC_16(saddr, gaddr) \
    asm volatile("cp.async.cg.shared.global [%0], [%1], 16;" \
                 :: "r"(saddr), "l"(gaddr) : "memory")
#define CP_COMMIT() asm volatile("cp.async.commit_group;" ::: "memory")
#define CP_WAIT2()  asm volatile("cp.async.wait_group 2;" ::: "memory")

#define MMA_S8(d0, d1, d2, d3, a0, a1, a2, a3, b0, b1) \
    asm volatile("mma.sync.aligned.m16n8k32.row.col.s32.s8.s8.s32 " \
                 "{%0,%1,%2,%3}, {%4,%5,%6,%7}, {%8,%9}, {%0,%1,%2,%3};" \
                 : "+r"(d0), "+r"(d1), "+r"(d2), "+r"(d3) \
                 : "r"(a0), "r"(a1), "r"(a2), "r"(a3), "r"(b0), "r"(b1))

__device__ __forceinline__ uint32_t lds32(uint32_t addr) {
    uint32_t v;
    asm volatile("ld.shared.b32 %0, [%1];" : "=r"(v) : "r"(addr));
    return v;
}

// ============================ conv kernel ============================
// CTA: 128 consecutive output pixels x all 256 couts. 256 threads = 8 warps
// in a 2(M) x 4(N) grid; warp tile 64(M) x 64(N).
// K = 18 chunks of 128B (9 taps x 2 ci-halves).
// SMEM stage: A 128 rows + B 256 rows, pitch 144B (row*36 words + tig covers
// all 32 banks across the 8 ldmatrix-group rows -> conflict-free LDS.32).
// Fragments loaded at the PTX-ISA documented (row, col) coordinates for
// mma.m16n8k32.s8. Output stored as FLOAT32 values (integer-exact).
static constexpr int PITCH       = 144;
static constexpr int BOFF        = 128 * PITCH;               // B region offset
static constexpr int STAGE_BYTES = (128 + 256) * PITCH;       // 55296
static constexpr int NUM_STAGES  = 3;
static constexpr int SMEM_DYN    = NUM_STAGES * STAGE_BYTES;  // 165888
static constexpr int NCHUNKS     = 18;

__global__ void __launch_bounds__(256, 1)
conv_kernel(float* __restrict__ out) {
    extern __shared__ uint8_t smem[];
    const uint32_t sbase = (uint32_t)__cvta_generic_to_shared(smem);

    const int tid  = threadIdx.x;
    const int lane = tid & 31;
    const int wid  = tid >> 5;
    const int warp_m = wid >> 2;       // 0..1  (64 M rows each)
    const int warp_n = wid & 3;        // 0..3  (64 couts each)
    const int g   = lane >> 2;         // group id 0..7
    const int tig = lane & 3;          // thread in group

    // ---------------- cp.async addressing ----------------
    const int arow  = tid & 127;
    const int ahalf = tid >> 7;                 // 0 or 1
    const int m_pix = blockIdx.x * 128 + arow;
    const int n_img = m_pix / (H_IMG * W_IMG);
    const int rem   = m_pix % (H_IMG * W_IMG);
    const int h_out = rem / W_IMG;
    const int w_out = rem % W_IMG;
    const uint8_t* a_gbase = g_xp +
        (((int64_t)n_img * H_PAD + h_out) * W_PAD + w_out) * C_IN;
    const uint32_t a_sbase = (uint32_t)(arow * PITCH + ahalf * 64);

    const uint8_t* b_gbase = g_w8 + (int64_t)tid * C_IN;
    const uint32_t b_sbase = (uint32_t)(BOFF + tid * PITCH);

    // ---------------- accumulators ----------------
    int d[4][8][4];
    #pragma unroll
    for (int mb = 0; mb < 4; mb++)
        #pragma unroll
        for (int nb = 0; nb < 8; nb++)
            #pragma unroll
            for (int q = 0; q < 4; q++) d[mb][nb][q] = 0;

    // ---------------- issue helper ----------------
    auto issue = [&](int s) {
        const int tap = s >> 1, ch = s & 1;
        const int kh = tap / 3, kw = tap % 3;
        const uint32_t stg = sbase + (s % NUM_STAGES) * STAGE_BYTES;
        const uint8_t* ga = a_gbase + ((int64_t)kh * W_PAD + kw) * C_IN
                          + ch * 128 + ahalf * 64;
        #pragma unroll
        for (int j = 0; j < 4; j++)
            CP_ASYNC_16(stg + a_sbase + j * 16, ga + j * 16);
        const uint8_t* gb = b_gbase + (int64_t)tap * (C_OUT * C_IN) + ch * 128;
        #pragma unroll
        for (int j = 0; j < 8; j++)
            CP_ASYNC_16(stg + b_sbase + j * 16, gb + j * 16);
    };

    issue(0); CP_COMMIT();
    issue(1); CP_COMMIT();
    issue(2); CP_COMMIT();

    // fragment base offsets (row part), col part added per ks
    uint32_t a_off[4];   // A[warp_m*64 + mb*16 + g][.]
    #pragma unroll
    for (int mb = 0; mb < 4; mb++)
        a_off[mb] = (uint32_t)((warp_m * 64 + mb * 16 + g) * PITCH + tig * 4);
    uint32_t b_off[8];   // Bt[warp_n*64 + nb*8 + g][.]
    #pragma unroll
    for (int nb = 0; nb < 8; nb++)
        b_off[nb] = (uint32_t)(BOFF + (warp_n * 64 + nb * 8 + g) * PITCH + tig * 4);

    // ---------------- main loop ----------------
    #pragma unroll 1
    for (int c = 0; c < NCHUNKS; c++) {
        CP_WAIT2();
        __syncthreads();
        const uint32_t stg = sbase + (c % NUM_STAGES) * STAGE_BYTES;

        #pragma unroll
        for (int ks = 0; ks < 4; ks++) {
            const uint32_t kcol = ks * 32;
            // A frags: a0=A[g][4t], a1=A[g+8][4t], a2=A[g][16+4t], a3=A[g+8][16+4t]
            uint32_t a[4][4];
            #pragma unroll
            for (int mb = 0; mb < 4; mb++) {
                const uint32_t p = stg + a_off[mb] + kcol;
                a[mb][0] = lds32(p);
                a[mb][1] = lds32(p + 8 * PITCH);
                a[mb][2] = lds32(p + 16);
                a[mb][3] = lds32(p + 8 * PITCH + 16);
            }
            // B frags: b0=Bt[g][4t], b1=Bt[g][16+4t]
            uint32_t b[8][2];
            #pragma unroll
            for (int nb = 0; nb < 8; nb++) {
                const uint32_t p = stg + b_off[nb] + kcol;
                b[nb][0] = lds32(p);
                b[nb][1] = lds32(p + 16);
            }
            #pragma unroll
            for (int mb = 0; mb < 4; mb++)
                #pragma unroll
                for (int nb = 0; nb < 8; nb++)
                    MMA_S8(d[mb][nb][0], d[mb][nb][1], d[mb][nb][2], d[mb][nb][3],
                           a[mb][0], a[mb][1], a[mb][2], a[mb][3],
                           b[nb][0], b[nb][1]);
        }

        __syncthreads();
        if (c + NUM_STAGES < NCHUNKS) issue(c + NUM_STAGES);
        CP_COMMIT();
    }

    // ---------------- epilogue: float32 VALUES (integer-exact) ----------------
    // c0 -> D[g][2t], c1 -> D[g][2t+1], c2 -> D[g+8][2t], c3 -> D[g+8][2t+1]
    #pragma unroll
    for (int mb = 0; mb < 4; mb++) {
        const int m0 = blockIdx.x * 128 + warp_m * 64 + mb * 16 + g;
        #pragma unroll
        for (int nb = 0; nb < 8; nb++) {
            const int co = warp_n * 64 + nb * 8 + tig * 2;
            *reinterpret_cast<float2*>(out + (int64_t)m0 * C_OUT + co) =
                make_float2(__int2float_rn(d[mb][nb][0]), __int2float_rn(d[mb][nb][1]));
            *reinterpret_cast<float2*>(out + (int64_t)(m0 + 8) * C_OUT + co) =
                make_float2(__int2float_rn(d[mb][nb][2]), __int2float_rn(d[mb][nb][3]));
        }
    }
}

// ============================ host launch ============================
extern "C" void kernel_launch(void* const* d_in, const int* in_sizes, int n_in,
                              void* d_out, int out_size) {
    (void)out_size;
    // Bind inputs BY SIZE: x has 51,380,224 elements, weight has 589,824.
    const int* x = (const int*)d_in[0];
    const int* w = (const int*)d_in[1];
    if (n_in >= 2 && in_sizes[0] < in_sizes[1]) {
        x = (const int*)d_in[1];
        w = (const int*)d_in[0];
    }
    float* out = (float*)d_out;

    const int64_t totalx = (int64_t)N_IMG * H_PAD * W_PAD * 64;
    pack_x_kernel<<<(unsigned)((totalx + 255) / 256), 256>>>(x);
    pack_w_kernel<<<(9 * C_OUT * 64 + 255) / 256, 256>>>(w);

    cudaFuncSetAttribute(conv_kernel, cudaFuncAttributeMaxDynamicSharedMemorySize, SMEM_DYN);
    const int grid = (N_IMG * H_IMG * W_IMG) / 128;  // 1568
    conv_kernel<<<grid, 256, SMEM_DYN>>>(out);
}

// round 9
// speedup vs baseline: 1.5115x; 1.5115x over previous
#include <cuda_runtime.h>
#include <cuda_bf16.h>
#include <mma.h>
#include <cstdint>

using namespace nvcuda;

// ============================ problem dims ============================
#define N_IMG 16
#define H_IMG 112
#define W_IMG 112
#define C_IN  256
#define C_OUT 256
#define H_PAD 114
#define W_PAD 114

// padded activations as bf16: [N][H_PAD][W_PAD][C_IN]  (~106 MB)
__device__ __align__(1024) __nv_bfloat16 g_xbf[(size_t)N_IMG * H_PAD * W_PAD * C_IN];
// weights as bf16, tap-major: [9][C_OUT][C_IN]
__device__ __align__(1024) __nv_bfloat16 g_wbf[9 * C_OUT * C_IN];

// ============================ pack kernels ============================
__global__ void pack_x_kernel(const int* __restrict__ x) {
    int64_t i = (int64_t)blockIdx.x * blockDim.x + threadIdx.x;
    const int64_t total = (int64_t)N_IMG * H_PAD * W_PAD * 64;  // 4-channel units
    if (i >= total) return;
    int c4 = (int)(i & 63);
    int64_t p = i >> 6;
    int wp = (int)(p % W_PAD);
    int64_t t = p / W_PAD;
    int hp = (int)(t % H_PAD);
    int n  = (int)(t / H_PAD);
    uint2 wout = make_uint2(0u, 0u);
    if (hp >= 1 && hp <= H_IMG && wp >= 1 && wp <= W_IMG) {
        const int4 v = *reinterpret_cast<const int4*>(
            x + ((((int64_t)n * H_IMG + (hp - 1)) * W_IMG + (wp - 1)) * C_IN + c4 * 4));
        __nv_bfloat162 p0 = __floats2bfloat162_rn((float)v.x, (float)v.y);
        __nv_bfloat162 p1 = __floats2bfloat162_rn((float)v.z, (float)v.w);
        wout.x = *reinterpret_cast<uint32_t*>(&p0);
        wout.y = *reinterpret_cast<uint32_t*>(&p1);
    }
    reinterpret_cast<uint2*>(g_xbf)[i] = wout;
}

__global__ void pack_w_kernel(const int* __restrict__ w) {
    int i = blockIdx.x * blockDim.x + threadIdx.x;
    const int total = 9 * C_OUT * 64;
    if (i >= total) return;
    int c4 = i & 63;
    int t = i >> 6;
    int co = t % C_OUT;
    int tap = t / C_OUT;  // kh*3 + kw
    const int4 v = *reinterpret_cast<const int4*>(
        w + (((int64_t)co * 9 + tap) * C_IN + c4 * 4));
    __nv_bfloat162 p0 = __floats2bfloat162_rn((float)v.x, (float)v.y);
    __nv_bfloat162 p1 = __floats2bfloat162_rn((float)v.z, (float)v.w);
    reinterpret_cast<uint2*>(g_wbf)[i] = make_uint2(
        *reinterpret_cast<uint32_t*>(&p0), *reinterpret_cast<uint32_t*>(&p1));
}

// ============================ asm helpers ============================
#define CP_ASYNC_16(saddr, gaddr) \
    asm volatile("cp.async.cg.shared.global [%0], [%1], 16;" \
                 :: "r"(saddr), "l"(gaddr) : "memory")
#define CP_COMMIT() asm volatile("cp.async.commit_group;" ::: "memory")
#define CP_WAIT2()  asm volatile("cp.async.wait_group 2;" ::: "memory")

// ============================ conv kernel ============================
// CTA: 128 consecutive output pixels x all 256 couts. 256 threads = 8 warps,
// 2(M) x 4(N) warp grid, warp tile 64x64 = 4x4 wmma 16x16x16 bf16 tiles.
// K = 36 chunks of 64 bf16 channels (9 taps x 4 ci-quarters) = 128B/row.
// Stage: A 128 rows + B 256 rows, pitch 144B (72 bf16; 16B-aligned for wmma,
// odd multiple of 16B -> LDSM row sets spread across all banks).
// Hot loop is pure cp.async (bf16 pre-packed in global) + wmma.
static constexpr int PITCH_E     = 72;                         // bf16 elems
static constexpr int PITCH_B     = 144;                        // bytes
static constexpr int B_OFF_E     = 128 * PITCH_E;              // 9216 elems
static constexpr int B_OFF_B     = 128 * PITCH_B;              // 18432 bytes
static constexpr int STAGE_E     = (128 + 256) * PITCH_E;      // 27648 elems
static constexpr int STAGE_B     = (128 + 256) * PITCH_B;      // 55296 bytes
static constexpr int NUM_STAGES  = 3;
static constexpr int SMEM_DYN    = NUM_STAGES * STAGE_B;       // 165888
static constexpr int NCHUNKS     = 36;

__global__ void __launch_bounds__(256, 1)
conv_kernel(float* __restrict__ out) {
    extern __shared__ __align__(128) __nv_bfloat16 sm[];
    const uint32_t sbase = (uint32_t)__cvta_generic_to_shared(sm);

    const int tid = threadIdx.x;
    const int wid = tid >> 5;
    const int wm  = wid >> 2;          // 0..1
    const int wn  = wid & 3;           // 0..3
    const int m_base = blockIdx.x * 128;

    // ---------------- cp.async addressing ----------------
    // A: row = tid & 127 (pixel), half = tid>>7 selects 64B half of 128B row.
    const int arow  = tid & 127;
    const int ahalf = tid >> 7;        // 0 or 1
    const int m_pix = m_base + arow;
    const int n_img = m_pix / (H_IMG * W_IMG);
    const int rem   = m_pix % (H_IMG * W_IMG);
    const int h_out = rem / W_IMG;
    const int w_out = rem % W_IMG;
    const __nv_bfloat16* a_gbase = g_xbf +
        (((int64_t)n_img * H_PAD + h_out) * W_PAD + w_out) * C_IN;
    const uint32_t a_sbase = (uint32_t)(arow * PITCH_B + ahalf * 64);

    // B: row = tid (cout 0..255), 8 x 16B per 128B row.
    const __nv_bfloat16* b_gbase = g_wbf + (int64_t)tid * C_IN;
    const uint32_t b_sbase = (uint32_t)(B_OFF_B + tid * PITCH_B);

    // ---------------- accumulators ----------------
    wmma::fragment<wmma::accumulator, 16, 16, 16, float> acc[4][4];
    #pragma unroll
    for (int mt = 0; mt < 4; mt++)
        #pragma unroll
        for (int nt = 0; nt < 4; nt++)
            wmma::fill_fragment(acc[mt][nt], 0.0f);

    // ---------------- issue helper ----------------
    // chunk s: tap = s>>2 (kh*3+kw), quarter = s&3 (64 channels = 128B)
    auto issue = [&](int s) {
        const int tap = s >> 2, ch = s & 3;
        const int kh = tap / 3, kw = tap % 3;
        const uint32_t stg = sbase + (s % NUM_STAGES) * STAGE_B;
        const uint8_t* ga = reinterpret_cast<const uint8_t*>(
            a_gbase + ((int64_t)kh * W_PAD + kw) * C_IN + ch * 64) + ahalf * 64;
        #pragma unroll
        for (int j = 0; j < 4; j++)
            CP_ASYNC_16(stg + a_sbase + j * 16, ga + j * 16);
        const uint8_t* gb = reinterpret_cast<const uint8_t*>(
            b_gbase + (int64_t)tap * (C_OUT * C_IN) + ch * 64);
        #pragma unroll
        for (int j = 0; j < 8; j++)
            CP_ASYNC_16(stg + b_sbase + j * 16, gb + j * 16);
    };

    issue(0); CP_COMMIT();
    issue(1); CP_COMMIT();
    issue(2); CP_COMMIT();

    // ---------------- main loop ----------------
    #pragma unroll 1
    for (int c = 0; c < NCHUNKS; c++) {
        CP_WAIT2();
        __syncthreads();
        const __nv_bfloat16* stg = sm + (c % NUM_STAGES) * STAGE_E;

        #pragma unroll
        for (int ks = 0; ks < 4; ks++) {
            wmma::fragment<wmma::matrix_a, 16, 16, 16, __nv_bfloat16,
                           wmma::row_major> af[4];
            #pragma unroll
            for (int mt = 0; mt < 4; mt++)
                wmma::load_matrix_sync(
                    af[mt], stg + (wm * 64 + mt * 16) * PITCH_E + ks * 16, PITCH_E);
            #pragma unroll
            for (int nt = 0; nt < 4; nt++) {
                wmma::fragment<wmma::matrix_b, 16, 16, 16, __nv_bfloat16,
                               wmma::col_major> bf;
                wmma::load_matrix_sync(
                    bf, stg + B_OFF_E + (wn * 64 + nt * 16) * PITCH_E + ks * 16,
                    PITCH_E);
                #pragma unroll
                for (int mt = 0; mt < 4; mt++)
                    wmma::mma_sync(acc[mt][nt], af[mt], bf, acc[mt][nt]);
            }
        }

        __syncthreads();
        if (c + NUM_STAGES < NCHUNKS) issue(c + NUM_STAGES);
        CP_COMMIT();
    }

    // ---------------- epilogue: float32 values (integer-exact) ----------------
    #pragma unroll
    for (int mt = 0; mt < 4; mt++)
        #pragma unroll
        for (int nt = 0; nt < 4; nt++) {
            float* dst = out
                       + (int64_t)(m_base + wm * 64 + mt * 16) * C_OUT
                       + wn * 64 + nt * 16;
            wmma::store_matrix_sync(dst, acc[mt][nt], C_OUT, wmma::mem_row_major);
        }
}

// ============================ host launch ============================
extern "C" void kernel_launch(void* const* d_in, const int* in_sizes, int n_in,
                              void* d_out, int out_size) {
    (void)out_size;
    // Bind inputs BY SIZE: x has 51,380,224 elements, weight has 589,824.
    const int* x = (const int*)d_in[0];
    const int* w = (const int*)d_in[1];
    if (n_in >= 2 && in_sizes[0] < in_sizes[1]) {
        x = (const int*)d_in[1];
        w = (const int*)d_in[0];
    }
    float* out = (float*)d_out;

    const int64_t totalx = (int64_t)N_IMG * H_PAD * W_PAD * 64;
    pack_x_kernel<<<(unsigned)((totalx + 255) / 256), 256>>>(x);
    pack_w_kernel<<<(9 * C_OUT * 64 + 255) / 256, 256>>>(w);

    cudaFuncSetAttribute(conv_kernel, cudaFuncAttributeMaxDynamicSharedMemorySize, SMEM_DYN);
    const int grid = (N_IMG * H_IMG * W_IMG) / 128;  // 1568
    conv_kernel<<<grid, 256, SMEM_DYN>>>(out);
}